// round 1
// baseline (speedup 1.0000x reference)
#include <cuda_runtime.h>
#include <cuda_bf16.h>
#include <cstdint>

// Problem constants
#define BB 64
#define TT 512
#define BT (BB*TT)          // 32768
#define GIN 1024            // INPUT + LATENT
#define HID 1024
#define H3  3072
#define NIN 512             // INPUT
#define KOUT 1536           // HID + INPUT
#define NCTA_GRU 128
#define NTHR_GRU 128

// ----------------------------- scratch (device globals; no cudaMalloc allowed)
__device__ float g_inp[(size_t)BT * GIN];     // [m][1024] = [emb(512) | z(512)]
__device__ float g_xproj[(size_t)BT * H3];    // [m][3072]
__device__ float g_hall[(size_t)BT * HID];    // [m][1024], m = b*T + t
__device__ unsigned g_bar;

// ----------------------------- helpers
__device__ __forceinline__ float to_tf32(float x) {
    unsigned u;
    asm("cvt.rna.tf32.f32 %0, %1;" : "=r"(u) : "f"(x));
    return __uint_as_float(u);
}

__device__ __forceinline__ void mma_tf32(float acc[4],
                                         const unsigned a[4],
                                         unsigned b0, unsigned b1) {
    asm volatile(
        "mma.sync.aligned.m16n8k8.row.col.f32.tf32.tf32.f32 "
        "{%0,%1,%2,%3},{%4,%5,%6,%7},{%8,%9},{%0,%1,%2,%3};"
        : "+f"(acc[0]), "+f"(acc[1]), "+f"(acc[2]), "+f"(acc[3])
        : "r"(a[0]), "r"(a[1]), "r"(a[2]), "r"(a[3]), "r"(b0), "r"(b1));
}

__device__ __forceinline__ float sigmoidf(float v) {
    return 1.0f / (1.0f + expf(-v));
}

// ----------------------------- kernel 1: gather emb + concat z ; reset barrier
__global__ void build_inp_kernel(const int* __restrict__ x,
                                 const float* __restrict__ z,
                                 const float* __restrict__ emb) {
    if (blockIdx.x == 0 && threadIdx.x == 0) g_bar = 0u;
    size_t idx = (size_t)blockIdx.x * 256 + threadIdx.x;   // < BT*GIN
    int m = (int)(idx >> 10);
    int k = (int)(idx & 1023);
    int b = m >> 9;
    float v;
    if (k < 512) v = emb[(size_t)x[m] * 512 + k];
    else         v = z[b * 512 + (k - 512)];
    g_inp[idx] = v;
}

// ----------------------------- tiled tf32 GEMM: C[M,N] = A[M,K] * W[N,K]^T + bias
// CAT: A-rows come from g_hall (k<1024, stride 1024) then g_inp emb part (k>=1024).
// TANH: apply tanh epilogue.
template<bool CAT, bool TANH>
__global__ void __launch_bounds__(256)
gemm_tf32_kernel(const float* __restrict__ A, const float* __restrict__ A2,
                 const float* __restrict__ W, const float* __restrict__ bias,
                 float* __restrict__ C, int M, int N, int K) {
    __shared__ float As[128][36];
    __shared__ float Bs[64][36];

    const int tid  = threadIdx.x;
    const int bN   = blockIdx.x;
    const int bM   = blockIdx.y;
    const int w    = tid >> 5;
    const int lane = tid & 31;
    const int wm   = w >> 1;       // 0..3
    const int wn   = w & 1;        // 0..1
    const int g    = lane >> 2;    // 0..7
    const int tig  = lane & 3;     // 0..3

    const int r8   = tid >> 3;          // 0..31
    const int cpos = (tid & 7) << 2;    // 0..28 step 4

    float acc[2][4][4];
#pragma unroll
    for (int mt = 0; mt < 2; ++mt)
#pragma unroll
        for (int nt = 0; nt < 4; ++nt)
#pragma unroll
            for (int i = 0; i < 4; ++i) acc[mt][nt][i] = 0.f;

    for (int k0 = 0; k0 < K; k0 += 32) {
        // load A tile 128x32
#pragma unroll
        for (int p = 0; p < 4; ++p) {
            int row = r8 + p * 32;
            size_t m = (size_t)bM * 128 + row;
            const float* src;
            if (CAT) {
                if (k0 < 1024) src = A  + m * 1024 + k0 + cpos;
                else           src = A2 + m * 1024 + (k0 - 1024) + cpos;
            } else {
                src = A + m * (size_t)K + k0 + cpos;
            }
            float4 v = *(const float4*)src;
            As[row][cpos + 0] = to_tf32(v.x);
            As[row][cpos + 1] = to_tf32(v.y);
            As[row][cpos + 2] = to_tf32(v.z);
            As[row][cpos + 3] = to_tf32(v.w);
        }
        // load B tile 64x32 (W rows are K-major)
#pragma unroll
        for (int p = 0; p < 2; ++p) {
            int n = r8 + p * 32;
            const float* src = W + ((size_t)bN * 64 + n) * (size_t)K + k0 + cpos;
            float4 v = *(const float4*)src;
            Bs[n][cpos + 0] = to_tf32(v.x);
            Bs[n][cpos + 1] = to_tf32(v.y);
            Bs[n][cpos + 2] = to_tf32(v.z);
            Bs[n][cpos + 3] = to_tf32(v.w);
        }
        __syncthreads();

#pragma unroll
        for (int kk = 0; kk < 4; ++kk) {
            const int kb = kk * 8;
            unsigned a[2][4], bb[4][2];
#pragma unroll
            for (int mt = 0; mt < 2; ++mt) {
                int r0 = wm * 32 + mt * 16 + g;
                a[mt][0] = __float_as_uint(As[r0    ][kb + tig    ]);
                a[mt][1] = __float_as_uint(As[r0 + 8][kb + tig    ]);
                a[mt][2] = __float_as_uint(As[r0    ][kb + tig + 4]);
                a[mt][3] = __float_as_uint(As[r0 + 8][kb + tig + 4]);
            }
#pragma unroll
            for (int nt = 0; nt < 4; ++nt) {
                int n0 = wn * 32 + nt * 8 + g;
                bb[nt][0] = __float_as_uint(Bs[n0][kb + tig    ]);
                bb[nt][1] = __float_as_uint(Bs[n0][kb + tig + 4]);
            }
#pragma unroll
            for (int mt = 0; mt < 2; ++mt)
#pragma unroll
                for (int nt = 0; nt < 4; ++nt)
                    mma_tf32(acc[mt][nt], a[mt], bb[nt][0], bb[nt][1]);
        }
        __syncthreads();
    }

    // epilogue
#pragma unroll
    for (int mt = 0; mt < 2; ++mt) {
#pragma unroll
        for (int nt = 0; nt < 4; ++nt) {
            int row = bM * 128 + wm * 32 + mt * 16 + g;
            int col = bN * 64 + wn * 32 + nt * 8 + 2 * tig;
            float b0 = bias[col], b1 = bias[col + 1];
            float v00 = acc[mt][nt][0] + b0;
            float v01 = acc[mt][nt][1] + b1;
            float v10 = acc[mt][nt][2] + b0;
            float v11 = acc[mt][nt][3] + b1;
            if (TANH) {
                v00 = tanhf(v00); v01 = tanhf(v01);
                v10 = tanhf(v10); v11 = tanhf(v11);
            }
            C[(size_t)row * N + col]           = v00;
            C[(size_t)row * N + col + 1]       = v01;
            C[(size_t)(row + 8) * N + col]     = v10;
            C[(size_t)(row + 8) * N + col + 1] = v11;
        }
    }
}

// ----------------------------- GRU persistent kernel
// 128 CTAs x 128 threads. CTA c owns hidden cols [c*8, c*8+8).
// W_hh slice (3 gates x 8 cols x 1024 K) pre-staged in shared as tf32 mma B-fragments.
// Per step: stage h[64,1024] in 8 chunks of 128 K, split-tf32 MMA (hi+lo), gates, grid barrier.
__global__ void __launch_bounds__(128)
gru_kernel(const float* __restrict__ Whh, const float* __restrict__ bhh,
           const int* __restrict__ x, const float* __restrict__ xproj,
           float* __restrict__ hall) {
    extern __shared__ float sm[];
    float* fragW = sm;                    // [128 ksteps][3 gates][64]
    float* Hs    = sm + 128 * 3 * 64;     // [64][132]
    float* bsl   = Hs + 64 * 132;         // [24]

    const int tid  = threadIdx.x;
    const int jc   = blockIdx.x * 8;
    const int w    = tid >> 5;
    const int lane = tid & 31;
    const int g    = lane >> 2;
    const int tig  = lane & 3;

    // one-time: W_hh slice -> B-fragment layout (tf32)
    for (int e = tid; e < 128 * 192; e += 128) {
        int ks   = e / 192;
        int r    = e % 192;
        int gate = r / 64;
        int pos  = r % 64;
        int half = pos >> 5;
        int t32  = pos & 31;
        int nl   = t32 >> 2;
        int kk   = ks * 8 + (t32 & 3) + half * 4;
        fragW[e] = to_tf32(Whh[(size_t)(gate * 1024 + jc + nl) * 1024 + kk]);
    }
    if (tid < 24) bsl[tid] = bhh[(tid >> 3) * 1024 + jc + (tid & 7)];
    __syncthreads();

    const int b0r = w * 16 + g;     // batch row for acc[.][0/1]
    const int b1r = b0r + 8;        // batch row for acc[.][2/3]
    const int j0  = jc + 2 * tig;
    const int j1  = j0 + 1;
    float bh[3][2];
#pragma unroll
    for (int gate = 0; gate < 3; ++gate) {
        bh[gate][0] = bsl[gate * 8 + 2 * tig];
        bh[gate][1] = bsl[gate * 8 + 2 * tig + 1];
    }

    for (int t = 0; t < TT; ++t) {
        float acc[3][4];
#pragma unroll
        for (int gate = 0; gate < 3; ++gate)
#pragma unroll
            for (int i = 0; i < 4; ++i) acc[gate][i] = 0.f;

        if (t > 0) {
            for (int kc = 0; kc < 8; ++kc) {
                // stage h chunk [64 rows][128 cols] (raw fp32, L2-only loads)
                for (int q = tid; q < 2048; q += 128) {
                    int row = q >> 5;
                    int c4  = (q & 31) << 2;
                    const float* src = hall + ((size_t)row * TT + (t - 1)) * 1024
                                            + kc * 128 + c4;
                    float4 v;
                    v.x = __ldcg(src + 0); v.y = __ldcg(src + 1);
                    v.z = __ldcg(src + 2); v.w = __ldcg(src + 3);
                    *(float4*)&Hs[row * 132 + c4] = v;
                }
                __syncthreads();
#pragma unroll 4
                for (int kl = 0; kl < 16; ++kl) {
                    const int kb = kl * 8;
                    float a_raw[4];
                    a_raw[0] = Hs[b0r * 132 + kb + tig];
                    a_raw[1] = Hs[b1r * 132 + kb + tig];
                    a_raw[2] = Hs[b0r * 132 + kb + tig + 4];
                    a_raw[3] = Hs[b1r * 132 + kb + tig + 4];
                    unsigned ahi[4], alo[4];
#pragma unroll
                    for (int i = 0; i < 4; ++i) {
                        float hi = to_tf32(a_raw[i]);
                        ahi[i] = __float_as_uint(hi);
                        alo[i] = __float_as_uint(to_tf32(a_raw[i] - hi));
                    }
                    const float* fw = fragW + (kc * 16 + kl) * 192;
#pragma unroll
                    for (int gate = 0; gate < 3; ++gate) {
                        unsigned bb0 = __float_as_uint(fw[gate * 64 + lane]);
                        unsigned bb1 = __float_as_uint(fw[gate * 64 + 32 + lane]);
                        mma_tf32(acc[gate], ahi, bb0, bb1);
                        mma_tf32(acc[gate], alo, bb0, bb1);
                    }
                }
                __syncthreads();
            }
        }

        // gates + state update: 4 (b,j) outputs per lane
        const int xi0 = x[b0r * TT + t];
        const int xi1 = x[b1r * TT + t];
#pragma unroll
        for (int c = 0; c < 4; ++c) {
            const int b = (c < 2) ? b0r : b1r;
            const int j = (c & 1) ? j1 : j0;
            const int jsel = c & 1;
            const bool msk = ((c < 2) ? xi0 : xi1) == 0;   // PAD == 0

            float hp = 0.f;
            if (t > 0) hp = __ldcg(hall + ((size_t)b * TT + (t - 1)) * 1024 + j);

            size_t xpb = ((size_t)b * TT + t) * (size_t)H3 + j;
            float xr = xproj[xpb];
            float xu = xproj[xpb + 1024];
            float xn = xproj[xpb + 2048];

            float hr = acc[0][c] + bh[0][jsel];
            float hu = acc[1][c] + bh[1][jsel];
            float hn = acc[2][c] + bh[2][jsel];

            float rr = sigmoidf(xr + hr);
            float uu = sigmoidf(xu + hu);
            float nn = tanhf(xn + rr * hn);
            float hv = (1.f - uu) * nn + uu * hp;
            if (msk) hv = hp;

            hall[((size_t)b * TT + t) * 1024 + j] = hv;
        }

        // grid barrier (sense via cumulative counter; g_bar reset by build_inp)
        __threadfence();
        __syncthreads();
        if (tid == 0) {
            atomicAdd(&g_bar, 1u);
            const unsigned tgt = (unsigned)gridDim.x * (unsigned)(t + 1);
            unsigned v;
            do {
                asm volatile("ld.acquire.gpu.u32 %0, [%1];"
                             : "=r"(v) : "l"(&g_bar) : "memory");
                if (v >= tgt) break;
                __nanosleep(64);
            } while (true);
        }
        __syncthreads();
    }
}

// ----------------------------- launch
extern "C" void kernel_launch(void* const* d_in, const int* in_sizes, int n_in,
                              void* d_out, int out_size) {
    const int*   x     = (const int*)d_in[0];
    const float* z     = (const float*)d_in[1];
    const float* emb   = (const float*)d_in[2];
    const float* W_ih  = (const float*)d_in[3];
    const float* b_ih  = (const float*)d_in[4];
    const float* W_hh  = (const float*)d_in[5];
    const float* b_hh  = (const float*)d_in[6];
    const float* W_out = (const float*)d_in[7];
    const float* b_out = (const float*)d_in[8];
    float* out = (float*)d_out;

    float *inp_p, *xproj_p, *hall_p;
    cudaGetSymbolAddress((void**)&inp_p,  g_inp);
    cudaGetSymbolAddress((void**)&xproj_p, g_xproj);
    cudaGetSymbolAddress((void**)&hall_p, g_hall);

    // 1. build inp (emb || z), reset barrier counter
    {
        size_t total = (size_t)BT * GIN;
        build_inp_kernel<<<(unsigned)(total / 256), 256>>>(x, z, emb);
    }

    // 2. x_proj = inp @ W_ih^T + b_ih   [32768 x 3072], K=1024
    {
        dim3 grid(H3 / 64, BT / 128);
        gemm_tf32_kernel<false, false><<<grid, 256>>>(
            inp_p, nullptr, W_ih, b_ih, xproj_p, BT, H3, GIN);
    }

    // 3. GRU recurrence (persistent, grid-barrier per step)
    {
        const int smem = (128 * 3 * 64 + 64 * 132 + 24) * 4;
        cudaFuncSetAttribute(gru_kernel,
                             cudaFuncAttributeMaxDynamicSharedMemorySize, smem);
        gru_kernel<<<NCTA_GRU, NTHR_GRU, smem>>>(W_hh, b_hh, x, xproj_p, hall_p);
    }

    // 4. logits = tanh([hidden|emb] @ W_out^T + b_out)   [32768 x 512], K=1536
    {
        dim3 grid(NIN / 64, BT / 128);
        gemm_tf32_kernel<true, true><<<grid, 256>>>(
            hall_p, inp_p, W_out, b_out, out, BT, NIN, KOUT);
    }
}

// round 3
// speedup vs baseline: 2.4838x; 2.4838x over previous
#include <cuda_runtime.h>
#include <cuda_bf16.h>
#include <cstdint>

// Problem constants
#define BB 64
#define TT 512
#define BT (BB*TT)          // 32768
#define GIN 1024
#define HID 1024
#define H3  3072
#define NIN 512
#define KOUT 1536

// ----------------------------- scratch (device globals)
__device__ float g_inp[(size_t)BT * GIN];                  // tf32-rounded [emb|z]
__device__ float g_xproj[(size_t)BT * H3];
__device__ float g_hall[(size_t)BT * HID];                 // tf32-rounded h, [b][t][H]
__device__ __nv_bfloat16 g_hhi[(size_t)TT * BB * HID];     // [t][b][H]
__device__ __nv_bfloat16 g_hlo[(size_t)TT * BB * HID];
__device__ float g_wih[(size_t)H3 * GIN];                  // tf32-rounded W_ih
__device__ float g_wout[(size_t)NIN * KOUT];               // tf32-rounded W_out
__device__ unsigned g_flags[128 * 8];                      // grid-barrier flags (32B apart)

// ----------------------------- helpers
__device__ __forceinline__ float to_tf32(float x) {
    unsigned u;
    asm("cvt.rna.tf32.f32 %0, %1;" : "=r"(u) : "f"(x));
    return __uint_as_float(u);
}
__device__ __forceinline__ void mma_tf32(float acc[4], const unsigned a[4],
                                         unsigned b0, unsigned b1) {
    asm volatile(
        "mma.sync.aligned.m16n8k8.row.col.f32.tf32.tf32.f32 "
        "{%0,%1,%2,%3},{%4,%5,%6,%7},{%8,%9},{%0,%1,%2,%3};"
        : "+f"(acc[0]), "+f"(acc[1]), "+f"(acc[2]), "+f"(acc[3])
        : "r"(a[0]), "r"(a[1]), "r"(a[2]), "r"(a[3]), "r"(b0), "r"(b1));
}
__device__ __forceinline__ void mma_bf16(float acc[4], const unsigned a[4],
                                         unsigned b0, unsigned b1) {
    asm volatile(
        "mma.sync.aligned.m16n8k16.row.col.f32.bf16.bf16.f32 "
        "{%0,%1,%2,%3},{%4,%5,%6,%7},{%8,%9},{%0,%1,%2,%3};"
        : "+f"(acc[0]), "+f"(acc[1]), "+f"(acc[2]), "+f"(acc[3])
        : "r"(a[0]), "r"(a[1]), "r"(a[2]), "r"(a[3]), "r"(b0), "r"(b1));
}
__device__ __forceinline__ void ldsm4(unsigned r[4], uint32_t addr) {
    asm volatile("ldmatrix.sync.aligned.m8n8.x4.shared.b16 {%0,%1,%2,%3}, [%4];"
                 : "=r"(r[0]), "=r"(r[1]), "=r"(r[2]), "=r"(r[3]) : "r"(addr));
}
__device__ __forceinline__ void ldsm2(unsigned r[2], uint32_t addr) {
    asm volatile("ldmatrix.sync.aligned.m8n8.x2.shared.b16 {%0,%1}, [%2];"
                 : "=r"(r[0]), "=r"(r[1]) : "r"(addr));
}
__device__ __forceinline__ uint32_t smem_u32(const void* p) {
    uint32_t a;
    asm("{ .reg .u64 t; cvta.to.shared.u64 t, %1; cvt.u32.u64 %0, t; }" : "=r"(a) : "l"(p));
    return a;
}
__device__ __forceinline__ void cpasync16(uint32_t dst, const void* src) {
    asm volatile("cp.async.cg.shared.global [%0], [%1], 16;" :: "r"(dst), "l"(src) : "memory");
}
__device__ __forceinline__ void cp_commit() {
    asm volatile("cp.async.commit_group;" ::: "memory");
}
__device__ __forceinline__ float sigmoidf(float v) { return 1.0f / (1.0f + expf(-v)); }
__device__ __forceinline__ uint32_t pk2(__nv_bfloat16 a, __nv_bfloat16 b) {
    __nv_bfloat162 t(a, b);
    return *(uint32_t*)&t;
}

// ----------------------------- kernel: gather emb + concat z (tf32) ; reset flags
__global__ void build_inp_kernel(const int* __restrict__ x,
                                 const float* __restrict__ z,
                                 const float* __restrict__ emb) {
    size_t idx = (size_t)blockIdx.x * 256 + threadIdx.x;
    if (idx < 1024) g_flags[idx] = 0u;
    int m = (int)(idx >> 10);
    int k = (int)(idx & 1023);
    int b = m >> 9;
    float v;
    if (k < 512) v = emb[(size_t)x[m] * 512 + k];
    else         v = z[b * 512 + (k - 512)];
    g_inp[idx] = to_tf32(v);
}

// ----------------------------- kernel: pre-round weights to tf32
__global__ void wprep_kernel(const float* __restrict__ Wih,
                             const float* __restrict__ Wout) {
    size_t idx = (size_t)blockIdx.x * 256 + threadIdx.x;
    const size_t NIH = (size_t)H3 * GIN;      // 3145728
    if (idx < NIH) g_wih[idx] = to_tf32(Wih[idx]);
    else           g_wout[idx - NIH] = to_tf32(Wout[idx - NIH]);
}

// ----------------------------- tf32 GEMM v2: C[M,N] = A[M,K]*W[N,K]^T + bias
// 128x128 CTA tile, 8 warps (warp 32x64), 3-stage cp.async, ldmatrix frags.
// Inputs already tf32-rounded. CAT: A k<1024 from A(stride 1024), k>=1024 from A2.
#define GSTG 36864              // per-stage bytes (A 18432 + B 18432), row stride 144
template<bool CAT, bool TANH>
__global__ void __launch_bounds__(256, 2)
gemm_v2(const float* __restrict__ A, const float* __restrict__ A2,
        const float* __restrict__ W, const float* __restrict__ bias,
        float* __restrict__ C, int N, int K) {
    extern __shared__ char smem[];
    const uint32_t sb = smem_u32(smem);
    const int tid  = threadIdx.x;
    const int lane = tid & 31;
    const int w    = tid >> 5;
    const int wm   = w >> 1;        // 0..3
    const int wn   = w & 1;         // 0..1
    const int bN   = blockIdx.x;
    const int bM   = blockIdx.y;
    const int S    = K >> 5;        // stages of k32

    float acc[2][8][4];
#pragma unroll
    for (int mt = 0; mt < 2; ++mt)
#pragma unroll
        for (int nt = 0; nt < 8; ++nt)
#pragma unroll
            for (int i = 0; i < 4; ++i) acc[mt][nt][i] = 0.f;

    auto stage = [&](int s) {
        const int k0 = s * 32;
        const uint32_t base = sb + (uint32_t)(s % 3) * GSTG;
#pragma unroll
        for (int it = 0; it < 4; ++it) {
            int o = tid + it * 256;             // 0..1023
            int row = o >> 3, seg = o & 7;
            size_t m = (size_t)bM * 128 + row;
            const float* srcA;
            if (CAT) {
                if (k0 < 1024) srcA = A  + m * 1024 + k0 + seg * 4;
                else           srcA = A2 + m * 1024 + (k0 - 1024) + seg * 4;
            } else {
                srcA = A + m * (size_t)K + k0 + seg * 4;
            }
            cpasync16(base + row * 144 + seg * 16, srcA);
            const float* srcB = W + ((size_t)bN * 128 + row) * (size_t)K + k0 + seg * 4;
            cpasync16(base + 18432 + row * 144 + seg * 16, srcB);
        }
        cp_commit();
    };

    stage(0); stage(1); stage(2);

    for (int s = 0; s < S; ++s) {
        asm volatile("cp.async.wait_group 2;" ::: "memory");
        __syncthreads();
        const uint32_t As = sb + (uint32_t)(s % 3) * GSTG;
        const uint32_t Bs = As + 18432;
        const uint32_t aAddr = As + (uint32_t)(wm * 32 + (lane & 15)) * 144 + (lane >> 4) * 16;
        const uint32_t bAddr = Bs + (uint32_t)(wn * 64 + (lane & 7)) * 144 + ((lane >> 3) & 1) * 16;
#pragma unroll
        for (int kk = 0; kk < 4; ++kk) {
            unsigned a[2][4], b[8][2];
#pragma unroll
            for (int mt = 0; mt < 2; ++mt)
                ldsm4(a[mt], aAddr + mt * 16 * 144 + kk * 32);
#pragma unroll
            for (int nt = 0; nt < 8; ++nt)
                ldsm2(b[nt], bAddr + nt * 8 * 144 + kk * 32);
#pragma unroll
            for (int mt = 0; mt < 2; ++mt)
#pragma unroll
                for (int nt = 0; nt < 8; ++nt)
                    mma_tf32(acc[mt][nt], a[mt], b[nt][0], b[nt][1]);
        }
        __syncthreads();
        if (s + 3 < S) stage(s + 3);
        else cp_commit();   // keep group counting symmetric
    }

    // epilogue
#pragma unroll
    for (int nt = 0; nt < 8; ++nt) {
        int col = bN * 128 + wn * 64 + nt * 8 + 2 * (lane & 3);
        float b0 = bias[col], b1 = bias[col + 1];
#pragma unroll
        for (int mt = 0; mt < 2; ++mt) {
            int row = bM * 128 + wm * 32 + mt * 16 + (lane >> 2);
            float v00 = acc[mt][nt][0] + b0;
            float v01 = acc[mt][nt][1] + b1;
            float v10 = acc[mt][nt][2] + b0;
            float v11 = acc[mt][nt][3] + b1;
            if (TANH) { v00 = tanhf(v00); v01 = tanhf(v01); v10 = tanhf(v10); v11 = tanhf(v11); }
            *(float2*)&C[(size_t)row * N + col]       = make_float2(v00, v01);
            *(float2*)&C[(size_t)(row + 8) * N + col] = make_float2(v10, v11);
        }
    }
}

// ----------------------------- GRU persistent kernel (legacy bf16 mma)
// 128 CTAs x 384 threads (12 warps). CTA owns 8 hidden cols (jc..jc+7).
// warp = (mt = wid&3 : 16 batch rows, gate = wid>>2). Full K=1024 per warp.
// W_hh slice pre-packed in SMEM as B-fragments (bf16 hi|lo, LDS.128 per k-tile).
// h(t-1) staged hi/lo via double-buffered cp.async chunks of k=128; A frags via ldmatrix.
// SMEM: W frags 98304 | A 4x17408 | preact 3*64*48
#define SM_W 0u
#define SM_A 98304u
#define SM_P 167936u
#define SMEM_GRU 177152

__global__ void __launch_bounds__(384, 1)
gru_kernel(const float* __restrict__ Whh, const float* __restrict__ bhh,
           const int* __restrict__ x, const float* __restrict__ xproj,
           float* __restrict__ hall,
           __nv_bfloat16* __restrict__ hhi, __nv_bfloat16* __restrict__ hlo) {
    extern __shared__ char smem[];
    const uint32_t sb = smem_u32(smem);
    const int tid  = threadIdx.x;
    const int wid  = tid >> 5;
    const int lane = tid & 31;
    const int mt   = wid & 3;
    const int gate = wid >> 2;     // 0..2
    const int jc   = blockIdx.x * 8;

    // ---- one-time: pack W_hh slice into B-fragment layout (bf16 hi|lo)
    for (int u = tid; u < 6144; u += 384) {
        int kt = u / 96;
        int rem = u % 96;
        int g = rem >> 5, l = rem & 31;
        int n = l >> 2;
        int kb = kt * 16 + (l & 3) * 2;
        const float* wr = Whh + (size_t)(g * 1024 + jc + n) * 1024;
        float w0 = wr[kb], w1 = wr[kb + 1], w2 = wr[kb + 8], w3 = wr[kb + 9];
        __nv_bfloat16 h0 = __float2bfloat16_rn(w0), h1 = __float2bfloat16_rn(w1);
        __nv_bfloat16 h2 = __float2bfloat16_rn(w2), h3 = __float2bfloat16_rn(w3);
        __nv_bfloat16 l0 = __float2bfloat16_rn(w0 - __bfloat162float(h0));
        __nv_bfloat16 l1 = __float2bfloat16_rn(w1 - __bfloat162float(h1));
        __nv_bfloat16 l2 = __float2bfloat16_rn(w2 - __bfloat162float(h2));
        __nv_bfloat16 l3 = __float2bfloat16_rn(w3 - __bfloat162float(h3));
        uint4 v;
        v.x = pk2(h0, h1); v.y = pk2(h2, h3);
        v.z = pk2(l0, l1); v.w = pk2(l2, l3);
        *(uint4*)(smem + SM_W + ((size_t)(kt * 3 + g) * 512) + (size_t)l * 16) = v;
    }
    __syncthreads();

    // epilogue-thread state (tid < 64 : batch row = tid)
    float hp[8];
    float br_[8], bu_[8], bn_[8];
    if (tid < 64) {
#pragma unroll
        for (int j = 0; j < 8; ++j) {
            hp[j] = 0.f;
            br_[j] = bhh[jc + j];
            bu_[j] = bhh[1024 + jc + j];
            bn_[j] = bhh[2048 + jc + j];
        }
    }

    const unsigned myflag = blockIdx.x;

    for (int t = 0; t < TT; ++t) {
        // ---- prefetch epilogue operands
        int xtok = 0;
        float4 xr0, xr1, xu0, xu1, xn0, xn1;
        if (tid < 64) {
            xtok = x[tid * TT + t];
            const float* xb = xproj + ((size_t)tid * TT + t) * H3 + jc;
            xr0 = *(const float4*)(xb);         xr1 = *(const float4*)(xb + 4);
            xu0 = *(const float4*)(xb + 1024);  xu1 = *(const float4*)(xb + 1028);
            xn0 = *(const float4*)(xb + 2048);  xn1 = *(const float4*)(xb + 2052);
        }

        float dsum[3][4] = {};
        if (t > 0) {
            const char* srh = (const char*)hhi + (size_t)(t - 1) * BB * HID * 2;
            const char* srl = (const char*)hlo + (size_t)(t - 1) * BB * HID * 2;

            auto stage = [&](int c) {
                const int buf = c & 1;
                const uint32_t dh = sb + SM_A + (uint32_t)(buf * 2 + 0) * 17408;
                const uint32_t dl = sb + SM_A + (uint32_t)(buf * 2 + 1) * 17408;
#pragma unroll
                for (int it = 0; it < 3; ++it) {
                    int o = tid + it * 384;
                    if (o < 1024) {
                        int row = o >> 4, seg = o & 15;
                        size_t soff = (size_t)row * 2048 + (size_t)c * 256 + seg * 16;
                        uint32_t doff = (uint32_t)row * 272 + seg * 16;
                        cpasync16(dh + doff, srh + soff);
                        cpasync16(dl + doff, srl + soff);
                    }
                }
                cp_commit();
            };

            float cHH[2][4] = {}, cHL[2][4] = {}, cLH[2][4] = {};

            stage(0); stage(1);
            for (int c = 0; c < 8; ++c) {
                if (c < 7) asm volatile("cp.async.wait_group 1;" ::: "memory");
                else       asm volatile("cp.async.wait_group 0;" ::: "memory");
                __syncthreads();
                const int buf = c & 1;
                const uint32_t ah = sb + SM_A + (uint32_t)(buf * 2 + 0) * 17408
                                  + (uint32_t)(mt * 16 + (lane & 15)) * 272 + (lane >> 4) * 16;
                const uint32_t al = ah + 17408;
                const uint32_t wb = sb + SM_W + (uint32_t)lane * 16;
#pragma unroll
                for (int kt = 0; kt < 8; ++kt) {
                    unsigned ahr[4], alr[4];
                    ldsm4(ahr, ah + kt * 32);
                    ldsm4(alr, al + kt * 32);
                    uint4 B = *(const uint4*)(smem + SM_W
                              + ((size_t)((c * 8 + kt) * 3 + gate) * 512) + (size_t)lane * 16);
                    (void)wb;
                    const int p = kt & 1;
                    mma_bf16(cHH[p], ahr, B.x, B.y);
                    mma_bf16(cHL[p], ahr, B.z, B.w);
                    mma_bf16(cLH[p], alr, B.x, B.y);
                }
                __syncthreads();
                if (c + 2 < 8) stage(c + 2);
            }
#pragma unroll
            for (int i = 0; i < 4; ++i)
                dsum[0][i] = cHH[0][i] + cHH[1][i] + cHL[0][i] + cHL[1][i]
                           + cLH[0][i] + cLH[1][i];
            // write preact to SMEM
            {
                uint32_t pa = sb + SM_P + (uint32_t)gate * 3072
                            + (uint32_t)(mt * 16 + (lane >> 2)) * 48 + (lane & 3) * 8;
                *(float2*)(smem + SM_P + (size_t)gate * 3072
                           + (size_t)(mt * 16 + (lane >> 2)) * 48 + (lane & 3) * 8)
                    = make_float2(dsum[0][0], dsum[0][1]);
                *(float2*)(smem + SM_P + (size_t)gate * 3072
                           + (size_t)(mt * 16 + 8 + (lane >> 2)) * 48 + (lane & 3) * 8)
                    = make_float2(dsum[0][2], dsum[0][3]);
                (void)pa;
            }
        }
        __syncthreads();

        // ---- epilogue: 64 threads, one batch row each
        if (tid < 64) {
            float dr[8] = {}, du[8] = {}, dn[8] = {};
            if (t > 0) {
                const float* p0 = (const float*)(smem + SM_P + (size_t)tid * 48);
                const float* p1 = (const float*)(smem + SM_P + 3072 + (size_t)tid * 48);
                const float* p2 = (const float*)(smem + SM_P + 6144 + (size_t)tid * 48);
#pragma unroll
                for (int j = 0; j < 8; ++j) { dr[j] = p0[j]; du[j] = p1[j]; dn[j] = p2[j]; }
            }
            float xr[8] = {xr0.x, xr0.y, xr0.z, xr0.w, xr1.x, xr1.y, xr1.z, xr1.w};
            float xu[8] = {xu0.x, xu0.y, xu0.z, xu0.w, xu1.x, xu1.y, xu1.z, xu1.w};
            float xn[8] = {xn0.x, xn0.y, xn0.z, xn0.w, xn1.x, xn1.y, xn1.z, xn1.w};
            const bool msk = (xtok == 0);   // PAD
            float hv[8];
#pragma unroll
            for (int j = 0; j < 8; ++j) {
                float rr = sigmoidf(xr[j] + dr[j] + br_[j]);
                float uu = sigmoidf(xu[j] + du[j] + bu_[j]);
                float nn = tanhf(xn[j] + rr * (dn[j] + bn_[j]));
                float h  = (1.f - uu) * nn + uu * hp[j];
                hv[j] = msk ? hp[j] : h;
                hp[j] = hv[j];
            }
            // hall (tf32-rounded, for out-GEMM)
            float* hd = hall + ((size_t)tid * TT + t) * HID + jc;
            *(float4*)hd = make_float4(to_tf32(hv[0]), to_tf32(hv[1]),
                                       to_tf32(hv[2]), to_tf32(hv[3]));
            *(float4*)(hd + 4) = make_float4(to_tf32(hv[4]), to_tf32(hv[5]),
                                             to_tf32(hv[6]), to_tf32(hv[7]));
            // hhi/hlo
            __nv_bfloat16 hb[8], lb[8];
#pragma unroll
            for (int j = 0; j < 8; ++j) {
                hb[j] = __float2bfloat16_rn(hv[j]);
                lb[j] = __float2bfloat16_rn(hv[j] - __bfloat162float(hb[j]));
            }
            uint4 uh, ul;
            uh.x = pk2(hb[0], hb[1]); uh.y = pk2(hb[2], hb[3]);
            uh.z = pk2(hb[4], hb[5]); uh.w = pk2(hb[6], hb[7]);
            ul.x = pk2(lb[0], lb[1]); ul.y = pk2(lb[2], lb[3]);
            ul.z = pk2(lb[4], lb[5]); ul.w = pk2(lb[6], lb[7]);
            *(uint4*)(hhi + ((size_t)t * BB + tid) * HID + jc) = uh;
            *(uint4*)(hlo + ((size_t)t * BB + tid) * HID + jc) = ul;
            __threadfence();
        }
        __syncthreads();

        // ---- grid barrier: flag write + warp-0 poll
        if (tid == 0) {
            asm volatile("st.release.gpu.global.u32 [%0], %1;"
                         :: "l"(&g_flags[myflag * 8]), "r"((unsigned)(t + 1)) : "memory");
        }
        if (wid == 0) {
            const unsigned tgt = (unsigned)(t + 1);
            for (;;) {
                unsigned v0, v1, v2, v3;
                const unsigned* f = &g_flags[lane * 32];     // 4 CTAs per lane, 8 u32 apart
                asm volatile("ld.acquire.gpu.global.u32 %0, [%1];" : "=r"(v0) : "l"(f));
                asm volatile("ld.acquire.gpu.global.u32 %0, [%1];" : "=r"(v1) : "l"(f + 8));
                asm volatile("ld.acquire.gpu.global.u32 %0, [%1];" : "=r"(v2) : "l"(f + 16));
                asm volatile("ld.acquire.gpu.global.u32 %0, [%1];" : "=r"(v3) : "l"(f + 24));
                bool ok = (v0 >= tgt) && (v1 >= tgt) && (v2 >= tgt) && (v3 >= tgt);
                if (__all_sync(0xFFFFFFFFu, ok)) break;
                __nanosleep(32);
            }
        }
        __syncthreads();
    }
}

// ----------------------------- launch
extern "C" void kernel_launch(void* const* d_in, const int* in_sizes, int n_in,
                              void* d_out, int out_size) {
    const int*   x     = (const int*)d_in[0];
    const float* z     = (const float*)d_in[1];
    const float* emb   = (const float*)d_in[2];
    const float* W_ih  = (const float*)d_in[3];
    const float* b_ih  = (const float*)d_in[4];
    const float* W_hh  = (const float*)d_in[5];
    const float* b_hh  = (const float*)d_in[6];
    const float* W_out = (const float*)d_in[7];
    const float* b_out = (const float*)d_in[8];
    float* out = (float*)d_out;

    float *inp_p, *xproj_p, *hall_p, *wih_p, *wout_p;
    __nv_bfloat16 *hhi_p, *hlo_p;
    cudaGetSymbolAddress((void**)&inp_p,   g_inp);
    cudaGetSymbolAddress((void**)&xproj_p, g_xproj);
    cudaGetSymbolAddress((void**)&hall_p,  g_hall);
    cudaGetSymbolAddress((void**)&wih_p,   g_wih);
    cudaGetSymbolAddress((void**)&wout_p,  g_wout);
    cudaGetSymbolAddress((void**)&hhi_p,   g_hhi);
    cudaGetSymbolAddress((void**)&hlo_p,   g_hlo);

    // 1. build inp (tf32'd emb||z), reset barrier flags
    build_inp_kernel<<<(unsigned)((size_t)BT * GIN / 256), 256>>>(x, z, emb);

    // 2. tf32-round weights
    wprep_kernel<<<(unsigned)(((size_t)H3 * GIN + (size_t)NIN * KOUT) / 256), 256>>>(W_ih, W_out);

    // 3. x_proj = inp @ W_ih^T + b_ih   [32768 x 3072], K=1024
    {
        cudaFuncSetAttribute(gemm_v2<false, false>,
                             cudaFuncAttributeMaxDynamicSharedMemorySize, 3 * GSTG);
        dim3 grid(H3 / 128, BT / 128);
        gemm_v2<false, false><<<grid, 256, 3 * GSTG>>>(
            inp_p, nullptr, wih_p, b_ih, xproj_p, H3, GIN);
    }

    // 4. GRU recurrence (persistent, flag grid-barrier per step)
    {
        cudaFuncSetAttribute(gru_kernel,
                             cudaFuncAttributeMaxDynamicSharedMemorySize, SMEM_GRU);
        gru_kernel<<<128, 384, SMEM_GRU>>>(W_hh, b_hh, x, xproj_p, hall_p, hhi_p, hlo_p);
    }

    // 5. logits = tanh([hidden|emb] @ W_out^T + b_out)   [32768 x 512], K=1536
    {
        cudaFuncSetAttribute(gemm_v2<true, true>,
                             cudaFuncAttributeMaxDynamicSharedMemorySize, 3 * GSTG);
        dim3 grid(NIN / 128, BT / 128);
        gemm_v2<true, true><<<grid, 256, 3 * GSTG>>>(
            hall_p, inp_p, wout_p, b_out, out, NIN, KOUT);
    }
}

// round 4
// speedup vs baseline: 2.6207x; 1.0551x over previous
#include <cuda_runtime.h>
#include <cuda_bf16.h>
#include <cuda_fp16.h>
#include <cstdint>

// Problem constants
#define BB 64
#define TT 512
#define BT (BB*TT)          // 32768
#define GIN 1024
#define HID 1024
#define H3  3072
#define NIN 512
#define KOUT 1536

// ----------------------------- scratch (device globals)
__device__ float g_inp[(size_t)BT * GIN];                  // tf32-rounded [emb|z]
__device__ float g_xproj[(size_t)BT * H3];
__device__ float g_hall[(size_t)BT * HID];                 // tf32-rounded h, [b][t][H]
__device__ __half g_hhi[(size_t)TT * BB * HID];            // [t][b][H] fp16 hi
__device__ __half g_hlo[(size_t)TT * BB * HID];            // fp16 lo
__device__ float g_wih[(size_t)H3 * GIN];                  // tf32-rounded W_ih
__device__ float g_wout[(size_t)NIN * KOUT];               // tf32-rounded W_out
__device__ unsigned g_flags[128 * 8];                      // grid-barrier flags (32B apart)

// ----------------------------- helpers
__device__ __forceinline__ float to_tf32(float x) {
    unsigned u;
    asm("cvt.rna.tf32.f32 %0, %1;" : "=r"(u) : "f"(x));
    return __uint_as_float(u);
}
__device__ __forceinline__ void mma_tf32(float acc[4], const unsigned a[4],
                                         unsigned b0, unsigned b1) {
    asm volatile(
        "mma.sync.aligned.m16n8k8.row.col.f32.tf32.tf32.f32 "
        "{%0,%1,%2,%3},{%4,%5,%6,%7},{%8,%9},{%0,%1,%2,%3};"
        : "+f"(acc[0]), "+f"(acc[1]), "+f"(acc[2]), "+f"(acc[3])
        : "r"(a[0]), "r"(a[1]), "r"(a[2]), "r"(a[3]), "r"(b0), "r"(b1));
}
__device__ __forceinline__ void mma_f16(float acc[4], const unsigned a[4],
                                        unsigned b0, unsigned b1) {
    asm volatile(
        "mma.sync.aligned.m16n8k16.row.col.f32.f16.f16.f32 "
        "{%0,%1,%2,%3},{%4,%5,%6,%7},{%8,%9},{%0,%1,%2,%3};"
        : "+f"(acc[0]), "+f"(acc[1]), "+f"(acc[2]), "+f"(acc[3])
        : "r"(a[0]), "r"(a[1]), "r"(a[2]), "r"(a[3]), "r"(b0), "r"(b1));
}
__device__ __forceinline__ void ldsm4(unsigned r[4], uint32_t addr) {
    asm volatile("ldmatrix.sync.aligned.m8n8.x4.shared.b16 {%0,%1,%2,%3}, [%4];"
                 : "=r"(r[0]), "=r"(r[1]), "=r"(r[2]), "=r"(r[3]) : "r"(addr));
}
__device__ __forceinline__ void ldsm2(unsigned r[2], uint32_t addr) {
    asm volatile("ldmatrix.sync.aligned.m8n8.x2.shared.b16 {%0,%1}, [%2];"
                 : "=r"(r[0]), "=r"(r[1]) : "r"(addr));
}
__device__ __forceinline__ uint32_t smem_u32(const void* p) {
    uint32_t a;
    asm("{ .reg .u64 t; cvta.to.shared.u64 t, %1; cvt.u32.u64 %0, t; }" : "=r"(a) : "l"(p));
    return a;
}
__device__ __forceinline__ void cpasync16(uint32_t dst, const void* src) {
    asm volatile("cp.async.cg.shared.global [%0], [%1], 16;" :: "r"(dst), "l"(src) : "memory");
}
__device__ __forceinline__ void cp_commit() {
    asm volatile("cp.async.commit_group;" ::: "memory");
}
__device__ __forceinline__ float sigmoidf(float v) { return 1.0f / (1.0f + expf(-v)); }
__device__ __forceinline__ uint32_t pk2h(__half a, __half b) {
    __half2 t(a, b);
    return *(uint32_t*)&t;
}

// ----------------------------- kernel: gather emb + concat z (tf32) ; reset flags
__global__ void build_inp_kernel(const int* __restrict__ x,
                                 const float* __restrict__ z,
                                 const float* __restrict__ emb) {
    size_t idx = (size_t)blockIdx.x * 256 + threadIdx.x;
    if (idx < 1024) g_flags[idx] = 0u;
    int m = (int)(idx >> 10);
    int k = (int)(idx & 1023);
    int b = m >> 9;
    float v;
    if (k < 512) v = emb[(size_t)x[m] * 512 + k];
    else         v = z[b * 512 + (k - 512)];
    g_inp[idx] = to_tf32(v);
}

// ----------------------------- kernel: pre-round weights to tf32
__global__ void wprep_kernel(const float* __restrict__ Wih,
                             const float* __restrict__ Wout) {
    size_t idx = (size_t)blockIdx.x * 256 + threadIdx.x;
    const size_t NIH = (size_t)H3 * GIN;
    if (idx < NIH) g_wih[idx] = to_tf32(Wih[idx]);
    else           g_wout[idx - NIH] = to_tf32(Wout[idx - NIH]);
}

// ----------------------------- tf32 GEMM v2 (unchanged from R3)
#define GSTG 36864
template<bool CAT, bool TANH>
__global__ void __launch_bounds__(256, 2)
gemm_v2(const float* __restrict__ A, const float* __restrict__ A2,
        const float* __restrict__ W, const float* __restrict__ bias,
        float* __restrict__ C, int N, int K) {
    extern __shared__ char smem[];
    const uint32_t sb = smem_u32(smem);
    const int tid  = threadIdx.x;
    const int lane = tid & 31;
    const int w    = tid >> 5;
    const int wm   = w >> 1;
    const int wn   = w & 1;
    const int bN   = blockIdx.x;
    const int bM   = blockIdx.y;
    const int S    = K >> 5;

    float acc[2][8][4];
#pragma unroll
    for (int mt = 0; mt < 2; ++mt)
#pragma unroll
        for (int nt = 0; nt < 8; ++nt)
#pragma unroll
            for (int i = 0; i < 4; ++i) acc[mt][nt][i] = 0.f;

    auto stage = [&](int s) {
        const int k0 = s * 32;
        const uint32_t base = sb + (uint32_t)(s % 3) * GSTG;
#pragma unroll
        for (int it = 0; it < 4; ++it) {
            int o = tid + it * 256;
            int row = o >> 3, seg = o & 7;
            size_t m = (size_t)bM * 128 + row;
            const float* srcA;
            if (CAT) {
                if (k0 < 1024) srcA = A  + m * 1024 + k0 + seg * 4;
                else           srcA = A2 + m * 1024 + (k0 - 1024) + seg * 4;
            } else {
                srcA = A + m * (size_t)K + k0 + seg * 4;
            }
            cpasync16(base + row * 144 + seg * 16, srcA);
            const float* srcB = W + ((size_t)bN * 128 + row) * (size_t)K + k0 + seg * 4;
            cpasync16(base + 18432 + row * 144 + seg * 16, srcB);
        }
        cp_commit();
    };

    stage(0); stage(1); stage(2);

    for (int s = 0; s < S; ++s) {
        asm volatile("cp.async.wait_group 2;" ::: "memory");
        __syncthreads();
        const uint32_t As = sb + (uint32_t)(s % 3) * GSTG;
        const uint32_t Bs = As + 18432;
        const uint32_t aAddr = As + (uint32_t)(wm * 32 + (lane & 15)) * 144 + (lane >> 4) * 16;
        const uint32_t bAddr = Bs + (uint32_t)(wn * 64 + (lane & 7)) * 144 + ((lane >> 3) & 1) * 16;
#pragma unroll
        for (int kk = 0; kk < 4; ++kk) {
            unsigned a[2][4], b[8][2];
#pragma unroll
            for (int mt = 0; mt < 2; ++mt)
                ldsm4(a[mt], aAddr + mt * 16 * 144 + kk * 32);
#pragma unroll
            for (int nt = 0; nt < 8; ++nt)
                ldsm2(b[nt], bAddr + nt * 8 * 144 + kk * 32);
#pragma unroll
            for (int mt = 0; mt < 2; ++mt)
#pragma unroll
                for (int nt = 0; nt < 8; ++nt)
                    mma_tf32(acc[mt][nt], a[mt], b[nt][0], b[nt][1]);
        }
        __syncthreads();
        if (s + 3 < S) stage(s + 3);
        else cp_commit();
    }

#pragma unroll
    for (int nt = 0; nt < 8; ++nt) {
        int col = bN * 128 + wn * 64 + nt * 8 + 2 * (lane & 3);
        float b0 = bias[col], b1 = bias[col + 1];
#pragma unroll
        for (int mt = 0; mt < 2; ++mt) {
            int row = bM * 128 + wm * 32 + mt * 16 + (lane >> 2);
            float v00 = acc[mt][nt][0] + b0;
            float v01 = acc[mt][nt][1] + b1;
            float v10 = acc[mt][nt][2] + b0;
            float v11 = acc[mt][nt][3] + b1;
            if (TANH) { v00 = tanhf(v00); v01 = tanhf(v01); v10 = tanhf(v10); v11 = tanhf(v11); }
            *(float2*)&C[(size_t)row * N + col]       = make_float2(v00, v01);
            *(float2*)&C[(size_t)(row + 8) * N + col] = make_float2(v10, v11);
        }
    }
}

// ----------------------------- GRU persistent kernel (fp16 2-pass)
// 128 CTAs x 384 threads (12 warps). CTA owns 8 hidden cols.
// warp = (mt = wid&3 : 16 batch rows, gate = wid>>2). Full K=1024 per warp.
// W_hh slice: fp16 single, B-fragment layout, 48KB.
// h(t-1): fp16 hi/lo, staged in 4 chunks of k=256, double-buffered cp.async.
// 2 MMA passes per k-tile: A_hi*W + A_lo*W.
// SMEM map:
//   SM_W = 0        : 49152  (64 ktiles x 3 gates x 256B)
//   SM_A = 49152    : 2 bufs x (hi 33792 + lo 33792) = 135168  (row stride 528)
//   SM_P = 184320   : preact 3 x 3072 = 9216
#define SM_W 0u
#define SM_A 49152u
#define ABUF 67584u
#define ALO  33792u
#define SM_P 184320u
#define SMEM_GRU 193536

__global__ void __launch_bounds__(384, 1)
gru_kernel(const float* __restrict__ Whh, const float* __restrict__ bhh,
           const int* __restrict__ x, const float* __restrict__ xproj,
           float* __restrict__ hall,
           __half* __restrict__ hhi, __half* __restrict__ hlo) {
    extern __shared__ char smem[];
    const uint32_t sb = smem_u32(smem);
    const int tid  = threadIdx.x;
    const int wid  = tid >> 5;
    const int lane = tid & 31;
    const int mt   = wid & 3;
    const int gate = wid >> 2;     // 0..2
    const int jc   = blockIdx.x * 8;

    // ---- one-time: pack W_hh slice into fp16 B-fragment layout (single precision pass)
    for (int u = tid; u < 6144; u += 384) {
        int kt = u / 96;
        int rem = u % 96;
        int g = rem >> 5, l = rem & 31;
        int n = l >> 2;
        int kb = kt * 16 + (l & 3) * 2;
        const float* wr = Whh + (size_t)(g * 1024 + jc + n) * 1024;
        float2 wa = *(const float2*)(wr + kb);
        float2 wb = *(const float2*)(wr + kb + 8);
        uint2 v;
        v.x = pk2h(__float2half_rn(wa.x), __float2half_rn(wa.y));
        v.y = pk2h(__float2half_rn(wb.x), __float2half_rn(wb.y));
        *(uint2*)(smem + SM_W + (size_t)(kt * 3 + g) * 256 + (size_t)l * 8) = v;
    }
    __syncthreads();

    // epilogue-thread state (tid < 64 : batch row = tid)
    float hp[8];
    float br_[8], bu_[8], bn_[8];
    if (tid < 64) {
#pragma unroll
        for (int j = 0; j < 8; ++j) {
            hp[j] = 0.f;
            br_[j] = bhh[jc + j];
            bu_[j] = bhh[1024 + jc + j];
            bn_[j] = bhh[2048 + jc + j];
        }
    }

    const unsigned myflag = blockIdx.x;

    for (int t = 0; t < TT; ++t) {
        // ---- prefetch epilogue operands
        int xtok = 0;
        float4 xr0, xr1, xu0, xu1, xn0, xn1;
        if (tid < 64) {
            xtok = x[tid * TT + t];
            const float* xb = xproj + ((size_t)tid * TT + t) * H3 + jc;
            xr0 = *(const float4*)(xb);         xr1 = *(const float4*)(xb + 4);
            xu0 = *(const float4*)(xb + 1024);  xu1 = *(const float4*)(xb + 1028);
            xn0 = *(const float4*)(xb + 2048);  xn1 = *(const float4*)(xb + 2052);
        }

        if (t > 0) {
            const char* srh = (const char*)(hhi + (size_t)(t - 1) * BB * HID);
            const char* srl = (const char*)(hlo + (size_t)(t - 1) * BB * HID);

            // stage chunk c (k = c*256 .. +256) into buffer c&1
            auto stage = [&](int c) {
                const uint32_t dh = sb + SM_A + (uint32_t)(c & 1) * ABUF;
#pragma unroll
                for (int it = 0; it < 6; ++it) {
                    int o = tid + it * 384;
                    if (o < 2048) {
                        int row = o >> 5, seg = o & 31;
                        size_t soff = (size_t)row * 2048 + (size_t)c * 512 + seg * 16;
                        uint32_t doff = (uint32_t)row * 528 + seg * 16;
                        cpasync16(dh + doff, srh + soff);
                        cpasync16(dh + ALO + doff, srl + soff);
                    }
                }
                cp_commit();
            };

            float cH[2][4] = {}, cL[2][4] = {};

            stage(0); stage(1);
            for (int c = 0; c < 4; ++c) {
                if (c < 3) asm volatile("cp.async.wait_group 1;" ::: "memory");
                else       asm volatile("cp.async.wait_group 0;" ::: "memory");
                __syncthreads();
                const uint32_t ah = sb + SM_A + (uint32_t)(c & 1) * ABUF
                                  + (uint32_t)(mt * 16 + (lane & 15)) * 528 + (lane >> 4) * 16;
#pragma unroll
                for (int kt = 0; kt < 16; ++kt) {
                    unsigned ahr[4], alr[4];
                    ldsm4(ahr, ah + kt * 32);
                    ldsm4(alr, ah + ALO + kt * 32);
                    uint2 B = *(const uint2*)(smem + SM_W
                              + (size_t)((c * 16 + kt) * 3 + gate) * 256 + (size_t)lane * 8);
                    const int p = kt & 1;
                    mma_f16(cH[p], ahr, B.x, B.y);
                    mma_f16(cL[p], alr, B.x, B.y);
                }
                __syncthreads();
                if (c + 2 < 4) stage(c + 2);
            }
            float dsum[4];
#pragma unroll
            for (int i = 0; i < 4; ++i)
                dsum[i] = cH[0][i] + cH[1][i] + cL[0][i] + cL[1][i];
            // write preact to SMEM: row = mt*16 + (lane>>2) (+8), cols 2*(lane&3)
            *(float2*)(smem + SM_P + (size_t)gate * 3072
                       + (size_t)(mt * 16 + (lane >> 2)) * 48 + (lane & 3) * 8)
                = make_float2(dsum[0], dsum[1]);
            *(float2*)(smem + SM_P + (size_t)gate * 3072
                       + (size_t)(mt * 16 + 8 + (lane >> 2)) * 48 + (lane & 3) * 8)
                = make_float2(dsum[2], dsum[3]);
        }
        __syncthreads();

        // ---- epilogue: 64 threads, one batch row each
        if (tid < 64) {
            float dr[8] = {}, du[8] = {}, dn[8] = {};
            if (t > 0) {
                const float* p0 = (const float*)(smem + SM_P + (size_t)tid * 48);
                const float* p1 = (const float*)(smem + SM_P + 3072 + (size_t)tid * 48);
                const float* p2 = (const float*)(smem + SM_P + 6144 + (size_t)tid * 48);
#pragma unroll
                for (int j = 0; j < 8; ++j) { dr[j] = p0[j]; du[j] = p1[j]; dn[j] = p2[j]; }
            }
            float xr[8] = {xr0.x, xr0.y, xr0.z, xr0.w, xr1.x, xr1.y, xr1.z, xr1.w};
            float xu[8] = {xu0.x, xu0.y, xu0.z, xu0.w, xu1.x, xu1.y, xu1.z, xu1.w};
            float xn[8] = {xn0.x, xn0.y, xn0.z, xn0.w, xn1.x, xn1.y, xn1.z, xn1.w};
            const bool msk = (xtok == 0);   // PAD
            float hv[8];
#pragma unroll
            for (int j = 0; j < 8; ++j) {
                float rr = sigmoidf(xr[j] + dr[j] + br_[j]);
                float uu = sigmoidf(xu[j] + du[j] + bu_[j]);
                float nn = tanhf(xn[j] + rr * (dn[j] + bn_[j]));
                float h  = (1.f - uu) * nn + uu * hp[j];
                hv[j] = msk ? hp[j] : h;
                hp[j] = hv[j];
            }
            // hall (tf32-rounded, for out-GEMM)
            float* hd = hall + ((size_t)tid * TT + t) * HID + jc;
            *(float4*)hd = make_float4(to_tf32(hv[0]), to_tf32(hv[1]),
                                       to_tf32(hv[2]), to_tf32(hv[3]));
            *(float4*)(hd + 4) = make_float4(to_tf32(hv[4]), to_tf32(hv[5]),
                                             to_tf32(hv[6]), to_tf32(hv[7]));
            // fp16 hi/lo
            __half hb[8], lb[8];
#pragma unroll
            for (int j = 0; j < 8; ++j) {
                hb[j] = __float2half_rn(hv[j]);
                lb[j] = __float2half_rn(hv[j] - __half2float(hb[j]));
            }
            uint4 uh, ul;
            uh.x = pk2h(hb[0], hb[1]); uh.y = pk2h(hb[2], hb[3]);
            uh.z = pk2h(hb[4], hb[5]); uh.w = pk2h(hb[6], hb[7]);
            ul.x = pk2h(lb[0], lb[1]); ul.y = pk2h(lb[2], lb[3]);
            ul.z = pk2h(lb[4], lb[5]); ul.w = pk2h(lb[6], lb[7]);
            *(uint4*)(hhi + ((size_t)t * BB + tid) * HID + jc) = uh;
            *(uint4*)(hlo + ((size_t)t * BB + tid) * HID + jc) = ul;
            __threadfence();
        }
        __syncthreads();

        // ---- grid barrier: flag write + warp-0 poll
        if (tid == 0) {
            asm volatile("st.release.gpu.global.u32 [%0], %1;"
                         :: "l"(&g_flags[myflag * 8]), "r"((unsigned)(t + 1)) : "memory");
        }
        if (wid == 0) {
            const unsigned tgt = (unsigned)(t + 1);
            for (;;) {
                unsigned v0, v1, v2, v3;
                const unsigned* f = &g_flags[lane * 32];
                asm volatile("ld.acquire.gpu.global.u32 %0, [%1];" : "=r"(v0) : "l"(f));
                asm volatile("ld.acquire.gpu.global.u32 %0, [%1];" : "=r"(v1) : "l"(f + 8));
                asm volatile("ld.acquire.gpu.global.u32 %0, [%1];" : "=r"(v2) : "l"(f + 16));
                asm volatile("ld.acquire.gpu.global.u32 %0, [%1];" : "=r"(v3) : "l"(f + 24));
                bool ok = (v0 >= tgt) && (v1 >= tgt) && (v2 >= tgt) && (v3 >= tgt);
                if (__all_sync(0xFFFFFFFFu, ok)) break;
                __nanosleep(32);
            }
        }
        __syncthreads();
    }
}

// ----------------------------- launch
extern "C" void kernel_launch(void* const* d_in, const int* in_sizes, int n_in,
                              void* d_out, int out_size) {
    const int*   x     = (const int*)d_in[0];
    const float* z     = (const float*)d_in[1];
    const float* emb   = (const float*)d_in[2];
    const float* W_ih  = (const float*)d_in[3];
    const float* b_ih  = (const float*)d_in[4];
    const float* W_hh  = (const float*)d_in[5];
    const float* b_hh  = (const float*)d_in[6];
    const float* W_out = (const float*)d_in[7];
    const float* b_out = (const float*)d_in[8];
    float* out = (float*)d_out;

    float *inp_p, *xproj_p, *hall_p, *wih_p, *wout_p;
    __half *hhi_p, *hlo_p;
    cudaGetSymbolAddress((void**)&inp_p,   g_inp);
    cudaGetSymbolAddress((void**)&xproj_p, g_xproj);
    cudaGetSymbolAddress((void**)&hall_p,  g_hall);
    cudaGetSymbolAddress((void**)&wih_p,   g_wih);
    cudaGetSymbolAddress((void**)&wout_p,  g_wout);
    cudaGetSymbolAddress((void**)&hhi_p,   g_hhi);
    cudaGetSymbolAddress((void**)&hlo_p,   g_hlo);

    // 1. build inp (tf32'd emb||z), reset barrier flags
    build_inp_kernel<<<(unsigned)((size_t)BT * GIN / 256), 256>>>(x, z, emb);

    // 2. tf32-round weights
    wprep_kernel<<<(unsigned)(((size_t)H3 * GIN + (size_t)NIN * KOUT) / 256), 256>>>(W_ih, W_out);

    // 3. x_proj = inp @ W_ih^T + b_ih   [32768 x 3072], K=1024
    {
        cudaFuncSetAttribute(gemm_v2<false, false>,
                             cudaFuncAttributeMaxDynamicSharedMemorySize, 3 * GSTG);
        dim3 grid(H3 / 128, BT / 128);
        gemm_v2<false, false><<<grid, 256, 3 * GSTG>>>(
            inp_p, nullptr, wih_p, b_ih, xproj_p, H3, GIN);
    }

    // 4. GRU recurrence (persistent, flag grid-barrier per step)
    {
        cudaFuncSetAttribute(gru_kernel,
                             cudaFuncAttributeMaxDynamicSharedMemorySize, SMEM_GRU);
        gru_kernel<<<128, 384, SMEM_GRU>>>(W_hh, b_hh, x, xproj_p, hall_p, hhi_p, hlo_p);
    }

    // 5. logits = tanh([hidden|emb] @ W_out^T + b_out)   [32768 x 512], K=1536
    {
        cudaFuncSetAttribute(gemm_v2<true, true>,
                             cudaFuncAttributeMaxDynamicSharedMemorySize, 3 * GSTG);
        dim3 grid(NIN / 128, BT / 128);
        gemm_v2<true, true><<<grid, 256, 3 * GSTG>>>(
            hall_p, inp_p, wout_p, b_out, out, NIN, KOUT);
    }
}

// round 5
// speedup vs baseline: 3.5155x; 1.3414x over previous
#include <cuda_runtime.h>
#include <cuda_bf16.h>
#include <cuda_fp16.h>
#include <cstdint>

// Problem constants
#define BB 64
#define TT 512
#define BT (BB*TT)          // 32768
#define GIN 1024
#define HID 1024
#define H3  3072
#define NIN 512
#define KOUT 1536

// ----------------------------- scratch (device globals)
__device__ float g_inp[(size_t)BT * GIN];                  // tf32-rounded [emb|z]
__device__ float g_xproj[(size_t)BT * H3];
__device__ float g_hall[(size_t)BT * HID];                 // tf32-rounded h, [b][t][H]
__device__ __half g_hhi[(size_t)TT * BB * HID];            // [t][b][H] fp16 hi
__device__ __half g_hlo[(size_t)TT * BB * HID];            // fp16 lo
__device__ float g_wih[(size_t)H3 * GIN];                  // tf32-rounded W_ih
__device__ float g_wout[(size_t)NIN * KOUT];               // tf32-rounded W_out
__device__ unsigned g_flags[128 * 8];                      // grid-barrier flags (32B apart)

// ----------------------------- helpers
__device__ __forceinline__ float to_tf32(float x) {
    unsigned u;
    asm("cvt.rna.tf32.f32 %0, %1;" : "=r"(u) : "f"(x));
    return __uint_as_float(u);
}
__device__ __forceinline__ void mma_tf32(float acc[4], const unsigned a[4],
                                         unsigned b0, unsigned b1) {
    asm volatile(
        "mma.sync.aligned.m16n8k8.row.col.f32.tf32.tf32.f32 "
        "{%0,%1,%2,%3},{%4,%5,%6,%7},{%8,%9},{%0,%1,%2,%3};"
        : "+f"(acc[0]), "+f"(acc[1]), "+f"(acc[2]), "+f"(acc[3])
        : "r"(a[0]), "r"(a[1]), "r"(a[2]), "r"(a[3]), "r"(b0), "r"(b1));
}
__device__ __forceinline__ void mma_f16(float acc[4], const unsigned a[4],
                                        unsigned b0, unsigned b1) {
    asm volatile(
        "mma.sync.aligned.m16n8k16.row.col.f32.f16.f16.f32 "
        "{%0,%1,%2,%3},{%4,%5,%6,%7},{%8,%9},{%0,%1,%2,%3};"
        : "+f"(acc[0]), "+f"(acc[1]), "+f"(acc[2]), "+f"(acc[3])
        : "r"(a[0]), "r"(a[1]), "r"(a[2]), "r"(a[3]), "r"(b0), "r"(b1));
}
__device__ __forceinline__ void ldsm4(unsigned r[4], uint32_t addr) {
    asm volatile("ldmatrix.sync.aligned.m8n8.x4.shared.b16 {%0,%1,%2,%3}, [%4];"
                 : "=r"(r[0]), "=r"(r[1]), "=r"(r[2]), "=r"(r[3]) : "r"(addr));
}
__device__ __forceinline__ void ldsm2(unsigned r[2], uint32_t addr) {
    asm volatile("ldmatrix.sync.aligned.m8n8.x2.shared.b16 {%0,%1}, [%2];"
                 : "=r"(r[0]), "=r"(r[1]) : "r"(addr));
}
__device__ __forceinline__ uint32_t smem_u32(const void* p) {
    uint32_t a;
    asm("{ .reg .u64 t; cvta.to.shared.u64 t, %1; cvt.u32.u64 %0, t; }" : "=r"(a) : "l"(p));
    return a;
}
__device__ __forceinline__ void cpasync16(uint32_t dst, const void* src) {
    asm volatile("cp.async.cg.shared.global [%0], [%1], 16;" :: "r"(dst), "l"(src) : "memory");
}
__device__ __forceinline__ void cp_commit() {
    asm volatile("cp.async.commit_group;" ::: "memory");
}
__device__ __forceinline__ float sigmoidf(float v) { return 1.0f / (1.0f + expf(-v)); }
__device__ __forceinline__ uint32_t pk2h(__half a, __half b) {
    __half2 t(a, b);
    return *(uint32_t*)&t;
}

// ----------------------------- kernel: gather emb + concat z (tf32) ; reset flags
__global__ void build_inp_kernel(const int* __restrict__ x,
                                 const float* __restrict__ z,
                                 const float* __restrict__ emb) {
    size_t idx = (size_t)blockIdx.x * 256 + threadIdx.x;
    if (idx < 1024) g_flags[idx] = 0u;
    int m = (int)(idx >> 10);
    int k = (int)(idx & 1023);
    int b = m >> 9;
    float v;
    if (k < 512) v = emb[(size_t)x[m] * 512 + k];
    else         v = z[b * 512 + (k - 512)];
    g_inp[idx] = to_tf32(v);
}

// ----------------------------- kernel: pre-round weights to tf32
__global__ void wprep_kernel(const float* __restrict__ Wih,
                             const float* __restrict__ Wout) {
    size_t idx = (size_t)blockIdx.x * 256 + threadIdx.x;
    const size_t NIH = (size_t)H3 * GIN;
    if (idx < NIH) g_wih[idx] = to_tf32(Wih[idx]);
    else           g_wout[idx - NIH] = to_tf32(Wout[idx - NIH]);
}

// ----------------------------- tf32 GEMM v2 (unchanged)
#define GSTG 36864
template<bool CAT, bool TANH>
__global__ void __launch_bounds__(256, 2)
gemm_v2(const float* __restrict__ A, const float* __restrict__ A2,
        const float* __restrict__ W, const float* __restrict__ bias,
        float* __restrict__ C, int N, int K) {
    extern __shared__ char smem[];
    const uint32_t sb = smem_u32(smem);
    const int tid  = threadIdx.x;
    const int lane = tid & 31;
    const int w    = tid >> 5;
    const int wm   = w >> 1;
    const int wn   = w & 1;
    const int bN   = blockIdx.x;
    const int bM   = blockIdx.y;
    const int S    = K >> 5;

    float acc[2][8][4];
#pragma unroll
    for (int mt = 0; mt < 2; ++mt)
#pragma unroll
        for (int nt = 0; nt < 8; ++nt)
#pragma unroll
            for (int i = 0; i < 4; ++i) acc[mt][nt][i] = 0.f;

    auto stage = [&](int s) {
        const int k0 = s * 32;
        const uint32_t base = sb + (uint32_t)(s % 3) * GSTG;
#pragma unroll
        for (int it = 0; it < 4; ++it) {
            int o = tid + it * 256;
            int row = o >> 3, seg = o & 7;
            size_t m = (size_t)bM * 128 + row;
            const float* srcA;
            if (CAT) {
                if (k0 < 1024) srcA = A  + m * 1024 + k0 + seg * 4;
                else           srcA = A2 + m * 1024 + (k0 - 1024) + seg * 4;
            } else {
                srcA = A + m * (size_t)K + k0 + seg * 4;
            }
            cpasync16(base + row * 144 + seg * 16, srcA);
            const float* srcB = W + ((size_t)bN * 128 + row) * (size_t)K + k0 + seg * 4;
            cpasync16(base + 18432 + row * 144 + seg * 16, srcB);
        }
        cp_commit();
    };

    stage(0); stage(1); stage(2);

    for (int s = 0; s < S; ++s) {
        asm volatile("cp.async.wait_group 2;" ::: "memory");
        __syncthreads();
        const uint32_t As = sb + (uint32_t)(s % 3) * GSTG;
        const uint32_t Bs = As + 18432;
        const uint32_t aAddr = As + (uint32_t)(wm * 32 + (lane & 15)) * 144 + (lane >> 4) * 16;
        const uint32_t bAddr = Bs + (uint32_t)(wn * 64 + (lane & 7)) * 144 + ((lane >> 3) & 1) * 16;
#pragma unroll
        for (int kk = 0; kk < 4; ++kk) {
            unsigned a[2][4], b[8][2];
#pragma unroll
            for (int mt = 0; mt < 2; ++mt)
                ldsm4(a[mt], aAddr + mt * 16 * 144 + kk * 32);
#pragma unroll
            for (int nt = 0; nt < 8; ++nt)
                ldsm2(b[nt], bAddr + nt * 8 * 144 + kk * 32);
#pragma unroll
            for (int mt = 0; mt < 2; ++mt)
#pragma unroll
                for (int nt = 0; nt < 8; ++nt)
                    mma_tf32(acc[mt][nt], a[mt], b[nt][0], b[nt][1]);
        }
        __syncthreads();
        if (s + 3 < S) stage(s + 3);
        else cp_commit();
    }

#pragma unroll
    for (int nt = 0; nt < 8; ++nt) {
        int col = bN * 128 + wn * 64 + nt * 8 + 2 * (lane & 3);
        float b0 = bias[col], b1 = bias[col + 1];
#pragma unroll
        for (int mt = 0; mt < 2; ++mt) {
            int row = bM * 128 + wm * 32 + mt * 16 + (lane >> 2);
            float v00 = acc[mt][nt][0] + b0;
            float v01 = acc[mt][nt][1] + b1;
            float v10 = acc[mt][nt][2] + b0;
            float v11 = acc[mt][nt][3] + b1;
            if (TANH) { v00 = tanhf(v00); v01 = tanhf(v01); v10 = tanhf(v10); v11 = tanhf(v11); }
            *(float2*)&C[(size_t)row * N + col]       = make_float2(v00, v01);
            *(float2*)&C[(size_t)(row + 8) * N + col] = make_float2(v10, v11);
        }
    }
}

// ----------------------------- GRU persistent kernel (batch-split groups)
// 4 groups x 32 CTAs. Group g owns batch rows [g*16, g*16+16); groups run
// INDEPENDENTLY (own 32-CTA flag barrier). CTA owns 32 hidden cols.
// W slice: 96 gate-rows x 1024 fp16 B-frags = 192KB SMEM-resident.
// h(t-1): 16 rows, fp16 hi/lo, 8 chunks of k=128, 3-buffer depth-2 cp.async.
// 12 warps: warp = (gate = wid>>2, colofs = (wid&3)*8). M=16 (one m16 tile).
// SMEM: W 196608 | A 3 x 8704 (hi 4352 + lo 4352, row stride 272) = 26112.
// preact [3][16][36]f aliases A buffer 0 (safe: buffer0 last read chunk 6,
// ordered before sync(7); preact written after MMA(7)).
#define SM_W 0u
#define SM_A 196608u
#define ABUF 8704u
#define SM_P 196608u
#define SMEM_GRU 222720

__global__ void __launch_bounds__(384, 1)
gru_kernel(const float* __restrict__ Whh, const float* __restrict__ bhh,
           const int* __restrict__ x, const float* __restrict__ xproj,
           float* __restrict__ hall,
           __half* __restrict__ hhi, __half* __restrict__ hlo) {
    extern __shared__ char smem[];
    const uint32_t sb = smem_u32(smem);
    const int tid   = threadIdx.x;
    const int wid   = tid >> 5;
    const int lane  = tid & 31;
    const int group = blockIdx.x >> 5;        // 0..3
    const int b0    = group * 16;
    const int jc    = (blockIdx.x & 31) * 32; // 32 hidden cols
    const int gate  = wid >> 2;               // 0..2
    const int colofs = (wid & 3) * 8;         // 0,8,16,24

    // ---- one-time: pack W_hh slice (96 rows x 1024) into fp16 B-fragments
    // layout: [64 kt][12 strips][32 lanes x uint2]
    for (int u = tid; u < 24576; u += 384) {
        int kt = u / 384;
        int rem = u % 384;
        int strip = rem >> 5, l = rem & 31;
        int g = strip >> 2, co = (strip & 3) * 8;
        int n = jc + co + (l >> 2);
        int k = kt * 16 + (l & 3) * 2;
        const float* wr = Whh + (size_t)(g * 1024 + n) * 1024;
        uint2 v;
        v.x = pk2h(__float2half_rn(wr[k]),     __float2half_rn(wr[k + 1]));
        v.y = pk2h(__float2half_rn(wr[k + 8]), __float2half_rn(wr[k + 9]));
        *(uint2*)(smem + SM_W + (size_t)(kt * 12 + strip) * 256 + (size_t)l * 8) = v;
    }
    __syncthreads();

    // ---- epilogue thread setup: tid<128, each owns (batch row, 4 cols)
    const int erow = tid >> 3;                // 0..15
    const int ec4  = (tid & 7) * 4;           // 0,4,..28
    const int eb   = b0 + erow;
    float hp[4] = {0.f, 0.f, 0.f, 0.f};
    float br_[4], bu_[4], bn_[4];
    if (tid < 128) {
#pragma unroll
        for (int j = 0; j < 4; ++j) {
            br_[j] = bhh[jc + ec4 + j];
            bu_[j] = bhh[1024 + jc + ec4 + j];
            bn_[j] = bhh[2048 + jc + ec4 + j];
        }
    }

    for (int t = 0; t < TT; ++t) {
        // ---- epilogue operand prefetch
        int xtok = 0;
        float4 xr, xu, xn;
        if (tid < 128) {
            xtok = x[eb * TT + t];
            const float* xb = xproj + ((size_t)eb * TT + t) * H3 + jc + ec4;
            xr = *(const float4*)xb;
            xu = *(const float4*)(xb + 1024);
            xn = *(const float4*)(xb + 2048);
        }

        if (t > 0) {
            auto stage = [&](int c) {
                if (tid < 256) {
                    int row = tid >> 4, seg = tid & 15;
                    size_t so = ((size_t)(t - 1) * BB + b0 + row) * HID + c * 128 + seg * 8;
                    uint32_t dst = sb + SM_A + (uint32_t)(c % 3) * ABUF
                                 + (uint32_t)row * 272 + seg * 16;
                    cpasync16(dst, hhi + so);
                    cpasync16(dst + 4352, hlo + so);
                }
                cp_commit();
            };

            float aH[2][4] = {}, aL[2][4] = {};
            stage(0); stage(1);
            for (int c = 0; c < 8; ++c) {
                if (c < 7) asm volatile("cp.async.wait_group 1;" ::: "memory");
                else       asm volatile("cp.async.wait_group 0;" ::: "memory");
                __syncthreads();
                if (c < 6) stage(c + 2);
                const uint32_t ah = sb + SM_A + (uint32_t)(c % 3) * ABUF
                                  + (uint32_t)(lane & 15) * 272 + (lane >> 4) * 16;
#pragma unroll
                for (int kt = 0; kt < 8; ++kt) {
                    unsigned hiF[4], loF[4];
                    ldsm4(hiF, ah + kt * 32);
                    ldsm4(loF, ah + 4352 + kt * 32);
                    uint2 B = *(const uint2*)(smem + SM_W
                              + (size_t)((c * 8 + kt) * 12 + wid) * 256 + (size_t)lane * 8);
                    const int p = kt & 1;
                    mma_f16(aH[p], hiF, B.x, B.y);
                    mma_f16(aL[p], loF, B.x, B.y);
                }
            }
            float ds[4];
#pragma unroll
            for (int i = 0; i < 4; ++i)
                ds[i] = aH[0][i] + aH[1][i] + aL[0][i] + aL[1][i];
            // preact write: [gate][16 rows][36 floats]
            {
                int r = lane >> 2;
                int col = colofs + 2 * (lane & 3);
                *(float2*)(smem + SM_P + (size_t)(gate * 16 + r) * 144 + (size_t)col * 4)
                    = make_float2(ds[0], ds[1]);
                *(float2*)(smem + SM_P + (size_t)(gate * 16 + r + 8) * 144 + (size_t)col * 4)
                    = make_float2(ds[2], ds[3]);
            }
        }
        __syncthreads();

        // ---- epilogue: 128 threads, (row, 4 cols) each
        if (tid < 128) {
            float dr[4] = {}, du[4] = {}, dn[4] = {};
            if (t > 0) {
                float4 v0 = *(const float4*)(smem + SM_P + (size_t)erow * 144 + ec4 * 4);
                float4 v1 = *(const float4*)(smem + SM_P + (size_t)(16 + erow) * 144 + ec4 * 4);
                float4 v2 = *(const float4*)(smem + SM_P + (size_t)(32 + erow) * 144 + ec4 * 4);
                dr[0] = v0.x; dr[1] = v0.y; dr[2] = v0.z; dr[3] = v0.w;
                du[0] = v1.x; du[1] = v1.y; du[2] = v1.z; du[3] = v1.w;
                dn[0] = v2.x; dn[1] = v2.y; dn[2] = v2.z; dn[3] = v2.w;
            }
            float xrv[4] = {xr.x, xr.y, xr.z, xr.w};
            float xuv[4] = {xu.x, xu.y, xu.z, xu.w};
            float xnv[4] = {xn.x, xn.y, xn.z, xn.w};
            const bool msk = (xtok == 0);   // PAD
            float hv[4];
#pragma unroll
            for (int j = 0; j < 4; ++j) {
                float rr = sigmoidf(xrv[j] + dr[j] + br_[j]);
                float uu = sigmoidf(xuv[j] + du[j] + bu_[j]);
                float nn = tanhf(xnv[j] + rr * (dn[j] + bn_[j]));
                float h  = (1.f - uu) * nn + uu * hp[j];
                hv[j] = msk ? hp[j] : h;
                hp[j] = hv[j];
            }
            // hall (tf32-rounded)
            *(float4*)(hall + ((size_t)eb * TT + t) * HID + jc + ec4)
                = make_float4(to_tf32(hv[0]), to_tf32(hv[1]), to_tf32(hv[2]), to_tf32(hv[3]));
            // fp16 hi/lo for next step
            __half hb[4], lb[4];
#pragma unroll
            for (int j = 0; j < 4; ++j) {
                hb[j] = __float2half_rn(hv[j]);
                lb[j] = __float2half_rn(hv[j] - __half2float(hb[j]));
            }
            uint2 uh, ul;
            uh.x = pk2h(hb[0], hb[1]); uh.y = pk2h(hb[2], hb[3]);
            ul.x = pk2h(lb[0], lb[1]); ul.y = pk2h(lb[2], lb[3]);
            *(uint2*)(hhi + ((size_t)t * BB + eb) * HID + jc + ec4) = uh;
            *(uint2*)(hlo + ((size_t)t * BB + eb) * HID + jc + ec4) = ul;
            __threadfence();
        }
        __syncthreads();

        // ---- group barrier: flag write + warp-0 poll (32 CTAs)
        if (tid == 0) {
            asm volatile("st.release.gpu.global.u32 [%0], %1;"
                         :: "l"(&g_flags[blockIdx.x * 8]), "r"((unsigned)(t + 1)) : "memory");
        }
        if (wid == 0) {
            const unsigned tgt = (unsigned)(t + 1);
            const unsigned* f = &g_flags[(group * 32 + lane) * 8];
            for (;;) {
                unsigned v;
                asm volatile("ld.acquire.gpu.global.u32 %0, [%1];" : "=r"(v) : "l"(f));
                if (__all_sync(0xFFFFFFFFu, v >= tgt)) break;
                __nanosleep(20);
            }
        }
        __syncthreads();
    }
}

// ----------------------------- launch
extern "C" void kernel_launch(void* const* d_in, const int* in_sizes, int n_in,
                              void* d_out, int out_size) {
    const int*   x     = (const int*)d_in[0];
    const float* z     = (const float*)d_in[1];
    const float* emb   = (const float*)d_in[2];
    const float* W_ih  = (const float*)d_in[3];
    const float* b_ih  = (const float*)d_in[4];
    const float* W_hh  = (const float*)d_in[5];
    const float* b_hh  = (const float*)d_in[6];
    const float* W_out = (const float*)d_in[7];
    const float* b_out = (const float*)d_in[8];
    float* out = (float*)d_out;

    float *inp_p, *xproj_p, *hall_p, *wih_p, *wout_p;
    __half *hhi_p, *hlo_p;
    cudaGetSymbolAddress((void**)&inp_p,   g_inp);
    cudaGetSymbolAddress((void**)&xproj_p, g_xproj);
    cudaGetSymbolAddress((void**)&hall_p,  g_hall);
    cudaGetSymbolAddress((void**)&wih_p,   g_wih);
    cudaGetSymbolAddress((void**)&wout_p,  g_wout);
    cudaGetSymbolAddress((void**)&hhi_p,   g_hhi);
    cudaGetSymbolAddress((void**)&hlo_p,   g_hlo);

    // 1. build inp (tf32'd emb||z), reset barrier flags
    build_inp_kernel<<<(unsigned)((size_t)BT * GIN / 256), 256>>>(x, z, emb);

    // 2. tf32-round weights
    wprep_kernel<<<(unsigned)(((size_t)H3 * GIN + (size_t)NIN * KOUT) / 256), 256>>>(W_ih, W_out);

    // 3. x_proj = inp @ W_ih^T + b_ih   [32768 x 3072], K=1024
    {
        cudaFuncSetAttribute(gemm_v2<false, false>,
                             cudaFuncAttributeMaxDynamicSharedMemorySize, 3 * GSTG);
        dim3 grid(H3 / 128, BT / 128);
        gemm_v2<false, false><<<grid, 256, 3 * GSTG>>>(
            inp_p, nullptr, wih_p, b_ih, xproj_p, H3, GIN);
    }

    // 4. GRU recurrence: 4 independent batch groups x 32 CTAs
    {
        cudaFuncSetAttribute(gru_kernel,
                             cudaFuncAttributeMaxDynamicSharedMemorySize, SMEM_GRU);
        gru_kernel<<<128, 384, SMEM_GRU>>>(W_hh, b_hh, x, xproj_p, hall_p, hhi_p, hlo_p);
    }

    // 5. logits = tanh([hidden|emb] @ W_out^T + b_out)   [32768 x 512], K=1536
    {
        cudaFuncSetAttribute(gemm_v2<true, true>,
                             cudaFuncAttributeMaxDynamicSharedMemorySize, 3 * GSTG);
        dim3 grid(NIN / 128, BT / 128);
        gemm_v2<true, true><<<grid, 256, 3 * GSTG>>>(
            hall_p, inp_p, wout_p, b_out, out, NIN, KOUT);
    }
}